// round 1
// baseline (speedup 1.0000x reference)
#include <cuda_runtime.h>
#include <cuda_bf16.h>
#include <math.h>

// ---------------------------------------------------------------------------
// Scratch (no dynamic allocation allowed): bilinear-folded tensor T and z buffer
// ---------------------------------------------------------------------------
__device__ float g_T2[16 * 16 * 16];      // T3[(m*16+k)*16 + c] = sum_a Wb[c,a,k]*Wb[a,c,m]
__device__ float g_zbuf[1 << 17];         // per-row z scalar (B <= 131072)

// ---------------------------------------------------------------------------
// Helpers
// ---------------------------------------------------------------------------
__device__ __forceinline__ float gelu_exact(float x) {
    return 0.5f * x * (1.0f + erff(x * 0.70710678118654752440f));
}

#define DUP2(d, x)                                                            \
    asm("mov.b64 %0, {%1, %2};"                                              \
        : "=l"(d) : "r"(__float_as_uint(x)), "r"(__float_as_uint(x)))

#define FMA2(acc, a, b)                                                       \
    asm("fma.rn.f32x2 %0, %1, %2, %0;" : "+l"(acc) : "l"(a), "l"(b))

#define UNPACK2(lo, hi, v)                                                    \
    asm("mov.b64 {%0, %1}, %2;" : "=f"(lo), "=f"(hi) : "l"(v))

// ---------------------------------------------------------------------------
// Kernel 1: fold the bilinear weights:
//   T[c,k,m] = sum_a Wb[c,a,k] * Wb[a,c,m]   (Wb row-major [i][j][k])
// stored as g_T2[(m*16+k)*16 + c] for vectorized reads in zpath.
// ---------------------------------------------------------------------------
__global__ void prep_T_kernel(const float* __restrict__ Wb) {
    int t = blockIdx.x * blockDim.x + threadIdx.x;
    if (t >= 4096) return;
    int c = t & 15;
    int k = (t >> 4) & 15;
    int m = (t >> 8) & 15;
    float acc = 0.0f;
#pragma unroll
    for (int a = 0; a < 16; a++) {
        acc = fmaf(Wb[c * 256 + a * 16 + k], Wb[a * 256 + c * 16 + m], acc);
    }
    g_T2[(m * 16 + k) * 16 + c] = acc;
}

// ---------------------------------------------------------------------------
// Kernel 2: z path (one thread per row).
//   e = emb[x]; h = relu(e@W1+b1)@W2+b2
//   z[c] = ob[c] + sum_{k,m} h0[k]*h1[m]*T[c,k,m]
//   zz   = relu(z@Wc1+bc1)@Wc2 + bc2   -> g_zbuf[b]
// All weight reads are warp-uniform smem broadcasts (conflict-free).
// ---------------------------------------------------------------------------
__global__ __launch_bounds__(256) void zpath_kernel(
    const int*   __restrict__ xg,
    const float* __restrict__ emb,
    const float* __restrict__ W1,  const float* __restrict__ b1,
    const float* __restrict__ W2,  const float* __restrict__ b2,
    const float* __restrict__ ob,
    const float* __restrict__ Wc1, const float* __restrict__ bc1,
    const float* __restrict__ Wc2, const float* __restrict__ bc2,
    int B)
{
    __shared__ float W1s[256], W2s[256], Wc1s[256];
    __shared__ float T3s[4096];
    __shared__ float b1s[16], b2s[16], obs[16], bc1s[16], Wc2s[16];
    __shared__ float bc2s;

    int tid = threadIdx.x;
    W1s[tid]  = W1[tid];
    W2s[tid]  = W2[tid];
    Wc1s[tid] = Wc1[tid];
    for (int i = tid; i < 4096; i += 256) T3s[i] = g_T2[i];
    if (tid < 16) {
        b1s[tid]  = b1[tid];
        b2s[tid]  = b2[tid];
        obs[tid]  = ob[tid];
        bc1s[tid] = bc1[tid];
        Wc2s[tid] = Wc2[tid];
    }
    if (tid == 0) bc2s = bc2[0];
    __syncthreads();

    int b = blockIdx.x * 256 + tid;
    if (b >= B) return;

    int2 xi = ((const int2*)xg)[b];

    float h0[16], h1[16];
#pragma unroll
    for (int s = 0; s < 2; s++) {
        long row = (s == 0) ? (long)xi.x : (long)xi.y;
        const float4* ep = (const float4*)(emb + row * 16);
        float4 E0 = ep[0], E1 = ep[1], E2 = ep[2], E3 = ep[3];
        float e[16] = {E0.x, E0.y, E0.z, E0.w, E1.x, E1.y, E1.z, E1.w,
                       E2.x, E2.y, E2.z, E2.w, E3.x, E3.y, E3.z, E3.w};
        float t[16];
#pragma unroll
        for (int j = 0; j < 16; j++) t[j] = b1s[j];
#pragma unroll
        for (int i = 0; i < 16; i++) {
            float ei = e[i];
#pragma unroll
            for (int j = 0; j < 16; j++) t[j] = fmaf(ei, W1s[i * 16 + j], t[j]);
        }
#pragma unroll
        for (int j = 0; j < 16; j++) t[j] = fmaxf(t[j], 0.0f);
        float* h = (s == 0) ? h0 : h1;
#pragma unroll
        for (int j = 0; j < 16; j++) h[j] = b2s[j];
#pragma unroll
        for (int i = 0; i < 16; i++) {
            float ti = t[i];
#pragma unroll
            for (int j = 0; j < 16; j++) h[j] = fmaf(ti, W2s[i * 16 + j], h[j]);
        }
    }

    float z[16];
#pragma unroll
    for (int c = 0; c < 16; c++) z[c] = obs[c];

    for (int m = 0; m < 16; m++) {           // dynamic loop (h1 -> local, cheap)
        float e1m = h1[m];
        const float4* tbase = (const float4*)&T3s[(m * 16) * 16];
#pragma unroll
        for (int k2 = 0; k2 < 16; k2++) {
            float o = h0[k2] * e1m;
            float4 ta = tbase[k2 * 4 + 0];
            float4 tb = tbase[k2 * 4 + 1];
            float4 tc = tbase[k2 * 4 + 2];
            float4 td = tbase[k2 * 4 + 3];
            z[0]  = fmaf(o, ta.x, z[0]);  z[1]  = fmaf(o, ta.y, z[1]);
            z[2]  = fmaf(o, ta.z, z[2]);  z[3]  = fmaf(o, ta.w, z[3]);
            z[4]  = fmaf(o, tb.x, z[4]);  z[5]  = fmaf(o, tb.y, z[5]);
            z[6]  = fmaf(o, tb.z, z[6]);  z[7]  = fmaf(o, tb.w, z[7]);
            z[8]  = fmaf(o, tc.x, z[8]);  z[9]  = fmaf(o, tc.y, z[9]);
            z[10] = fmaf(o, tc.z, z[10]); z[11] = fmaf(o, tc.w, z[11]);
            z[12] = fmaf(o, td.x, z[12]); z[13] = fmaf(o, td.y, z[13]);
            z[14] = fmaf(o, td.z, z[14]); z[15] = fmaf(o, td.w, z[15]);
        }
    }

    float zz = bc2s;
#pragma unroll
    for (int j = 0; j < 16; j++) {
        float a = bc1s[j];
#pragma unroll
        for (int c = 0; c < 16; c++) a = fmaf(z[c], Wc1s[c * 16 + j], a);
        a = fmaxf(a, 0.0f);
        zz = fmaf(a, Wc2s[j], zz);
    }
    g_zbuf[b] = zz;
}

// ---------------------------------------------------------------------------
// Kernel 3: fused pheno path + final combine.
//   g1[b,k] = gelu(ph0*Wp1[0,k] + ph1*Wp1[1,k])   (computed on the fly)
//   C[b,:]  = g1[b,:] @ Wp2        (fp32 FFMA2 register-tiled GEMM)
//   p[b]    = sum_j gelu(C[b,j])*Wp3[j] + bp3
//   out[b]  = g_zbuf[b] + p[b]
// CTA: 512 threads, 64 rows x 512 cols. Thread tile: 8 rows x 8 cols
// (accumulators as f32x2 pairs). KC=8 double-buffered smem.
// ---------------------------------------------------------------------------
#define RPB 64
#define KC  8
#define NCH (512 / KC)

__global__ __launch_bounds__(512, 1) void gemm_pheno_kernel(
    const float* __restrict__ phenos,
    const float* __restrict__ Wp1,
    const float* __restrict__ Wp2,
    const float* __restrict__ Wp3,
    const float* __restrict__ bp3,
    float* __restrict__ out,
    int B)
{
    __shared__ float  wsm[2][KC][512];   // Wp2 tile (also reused as reduction buf)
    __shared__ float  gsm[2][KC][RPB];   // g1 tile
    __shared__ float  wp1s[2][512];
    __shared__ float  wp3s[512];
    __shared__ float2 ph2[RPB];

    int tid = threadIdx.x;
    int rowbase = blockIdx.x * RPB;

    wp1s[0][tid] = Wp1[tid];
    wp1s[1][tid] = Wp1[512 + tid];
    wp3s[tid]    = Wp3[tid];
    if (tid < RPB) {
        int rb = rowbase + tid;
        ph2[tid] = (rb < B) ? ((const float2*)phenos)[rb] : make_float2(0.f, 0.f);
    }
    __syncthreads();

    int cg = tid >> 3;   // 0..63, owns cols [cg*8, cg*8+8)
    int rg = tid & 7;    // 0..7,  owns rows [rg*8, rg*8+8)
    int gk = tid >> 6;   // 0..7  (tile-fill k)
    int gr = tid & 63;   // 0..63 (tile-fill row)

    unsigned long long acc[8][4];
#pragma unroll
    for (int r = 0; r < 8; r++)
#pragma unroll
        for (int j = 0; j < 4; j++) acc[r][j] = 0ull;

    // fill first tile
    {
        const float4* src = (const float4*)Wp2;
        ((float4*)&wsm[0][0][0])[tid]       = src[tid];
        ((float4*)&wsm[0][0][0])[tid + 512] = src[tid + 512];
        float2 p = ph2[gr];
        float u = fmaf(p.y, wp1s[1][gk], p.x * wp1s[0][gk]);
        gsm[0][gk][gr] = gelu_exact(u);
    }
    __syncthreads();

    int buf = 0;
    for (int ch = 0; ch < NCH; ch++) {
        float4 wr0, wr1;
        float  gnext = 0.0f;
        bool   has_next = (ch + 1 < NCH);
        if (has_next) {
            const float4* src = (const float4*)(Wp2 + (ch + 1) * KC * 512);
            wr0 = src[tid];
            wr1 = src[tid + 512];
            int k0 = (ch + 1) * KC + gk;
            float2 p = ph2[gr];
            float u = fmaf(p.y, wp1s[1][k0], p.x * wp1s[0][k0]);
            gnext = gelu_exact(u);
        }

#pragma unroll
        for (int kk = 0; kk < KC; kk++) {
            const float4* gp = (const float4*)&gsm[buf][kk][rg * 8];
            float4 ga = gp[0], gb = gp[1];
            float gv[8] = {ga.x, ga.y, ga.z, ga.w, gb.x, gb.y, gb.z, gb.w};
            unsigned long long gq[8];
#pragma unroll
            for (int r = 0; r < 8; r++) DUP2(gq[r], gv[r]);

            const unsigned long long* wp =
                (const unsigned long long*)&wsm[buf][kk][cg * 8];
            unsigned long long w0 = wp[0], w1 = wp[1], w2 = wp[2], w3 = wp[3];

#pragma unroll
            for (int r = 0; r < 8; r++) {
                FMA2(acc[r][0], gq[r], w0);
                FMA2(acc[r][1], gq[r], w1);
                FMA2(acc[r][2], gq[r], w2);
                FMA2(acc[r][3], gq[r], w3);
            }
        }
        __syncthreads();
        if (has_next) {
            ((float4*)&wsm[buf ^ 1][0][0])[tid]       = wr0;
            ((float4*)&wsm[buf ^ 1][0][0])[tid + 512] = wr1;
            gsm[buf ^ 1][gk][gr] = gnext;
        }
        __syncthreads();
        buf ^= 1;
    }

    // ---- epilogue: gelu + Wp3 contraction + deterministic reduction ----
    float wv[8];
#pragma unroll
    for (int j = 0; j < 8; j++) wv[j] = wp3s[cg * 8 + j];

    float* red = (float*)&wsm[0][0][0];  // [64][65] padded, 4160 floats < 8192

#pragma unroll
    for (int r = 0; r < 8; r++) {
        float p = 0.0f;
#pragma unroll
        for (int jp = 0; jp < 4; jp++) {
            float lo, hi;
            UNPACK2(lo, hi, acc[r][jp]);
            p = fmaf(gelu_exact(lo), wv[2 * jp], p);
            p = fmaf(gelu_exact(hi), wv[2 * jp + 1], p);
        }
        red[(rg * 8 + r) * 65 + cg] = p;
    }
    __syncthreads();

    if (tid < RPB) {
        int b = rowbase + tid;
        if (b < B) {
            float s = 0.0f;
#pragma unroll 8
            for (int c = 0; c < 64; c++) s += red[tid * 65 + c];
            out[b] = g_zbuf[b] + s + bp3[0];
        }
    }
}

// ---------------------------------------------------------------------------
// Launch
// ---------------------------------------------------------------------------
extern "C" void kernel_launch(void* const* d_in, const int* in_sizes, int n_in,
                              void* d_out, int out_size) {
    const int*   x      = (const int*)  d_in[0];
    const float* phenos = (const float*)d_in[1];
    const float* emb    = (const float*)d_in[2];
    const float* W1     = (const float*)d_in[3];
    const float* b1     = (const float*)d_in[4];
    const float* W2     = (const float*)d_in[5];
    const float* b2     = (const float*)d_in[6];
    const float* Wb     = (const float*)d_in[7];
    const float* ob     = (const float*)d_in[8];
    const float* Wc1    = (const float*)d_in[9];
    const float* bc1    = (const float*)d_in[10];
    const float* Wc2    = (const float*)d_in[11];
    const float* bc2    = (const float*)d_in[12];
    const float* Wp1    = (const float*)d_in[13];
    const float* Wp2    = (const float*)d_in[14];
    const float* Wp3    = (const float*)d_in[15];
    const float* bp3    = (const float*)d_in[16];
    float* out = (float*)d_out;

    int B = in_sizes[0] / 2;

    prep_T_kernel<<<16, 256>>>(Wb);
    zpath_kernel<<<(B + 255) / 256, 256>>>(x, emb, W1, b1, W2, b2, ob,
                                           Wc1, bc1, Wc2, bc2, B);
    gemm_pheno_kernel<<<(B + RPB - 1) / RPB, 512>>>(phenos, Wp1, Wp2, Wp3,
                                                    bp3, out, B);
}

// round 3
// speedup vs baseline: 2.3157x; 2.3157x over previous
#include <cuda_runtime.h>
#include <cuda_bf16.h>
#include <math.h>
#include <stdint.h>

// ---------------------------------------------------------------------------
// Device scratch (declared statically; no dynamic allocation)
// ---------------------------------------------------------------------------
__device__ float g_T2[4096];                    // folded bilinear tensor
__device__ float g_zbuf[1 << 17];               // per-row z scalar
__device__ __nv_bfloat16 g_Wh[512 * 512];       // Wp2 split hi (layout [k][n])
__device__ __nv_bfloat16 g_Wl[512 * 512];       // Wp2 split lo (layout [k][n])

// ---------------------------------------------------------------------------
// Helpers
// ---------------------------------------------------------------------------
__device__ __forceinline__ uint32_t smem_u32(const void* p) {
    uint32_t a;
    asm("{ .reg .u64 t; cvta.to.shared.u64 t, %1; cvt.u32.u64 %0, t; }"
        : "=r"(a) : "l"(p));
    return a;
}

// Branch-free gelu, exact-erf via Abramowitz-Stegun 7.1.26 (|err| <= 1.5e-7)
__device__ __forceinline__ float gelu_fast(float x) {
    float ax = fabsf(x);
    float z  = ax * 0.70710678118654752440f;
    float t  = __fdividef(1.0f, fmaf(0.3275911f, z, 1.0f));
    float e  = __expf(-z * z);
    float y  = fmaf(t, 1.061405429f, -1.453152027f);
    y = fmaf(y, t, 1.421413741f);
    y = fmaf(y, t, -0.284496736f);
    y = fmaf(y, t, 0.254829592f);
    y = y * t * e;                       // 1 - erf(z)
    float erfv = 1.0f - y;               // erf(|x|/sqrt(2))
    return 0.5f * fmaf(ax, erfv, x);
}

#define LDMX4(r0, r1, r2, r3, a)                                              \
    asm volatile("ldmatrix.sync.aligned.m8n8.x4.shared.b16 {%0,%1,%2,%3}, [%4];" \
                 : "=r"(r0), "=r"(r1), "=r"(r2), "=r"(r3) : "r"(a))

#define LDMX4T(r0, r1, r2, r3, a)                                             \
    asm volatile("ldmatrix.sync.aligned.m8n8.x4.trans.shared.b16 {%0,%1,%2,%3}, [%4];" \
                 : "=r"(r0), "=r"(r1), "=r"(r2), "=r"(r3) : "r"(a))

#define MMA16816(d, a, b)                                                     \
    asm("mma.sync.aligned.m16n8k16.row.col.f32.bf16.bf16.f32 "               \
        "{%0,%1,%2,%3}, {%4,%5,%6,%7}, {%8,%9}, {%0,%1,%2,%3};"               \
        : "+f"((d)[0]), "+f"((d)[1]), "+f"((d)[2]), "+f"((d)[3])              \
        : "r"((a)[0]), "r"((a)[1]), "r"((a)[2]), "r"((a)[3]),                 \
          "r"((b)[0]), "r"((b)[1]))

#define CP_ASYNC16(dst, src)                                                  \
    asm volatile("cp.async.cg.shared.global [%0], [%1], 16;"                  \
                 :: "r"(dst), "l"(src) : "memory")

#define CP_COMMIT() asm volatile("cp.async.commit_group;" ::: "memory")
#define CP_WAIT1()  asm volatile("cp.async.wait_group 1;" ::: "memory")

// ---------------------------------------------------------------------------
// prep_T: T[c,k,m] = sum_a Wb[c,a,k]*Wb[a,c,m]
// ---------------------------------------------------------------------------
__global__ void prep_T_kernel(const float* __restrict__ Wb) {
    int t = blockIdx.x * blockDim.x + threadIdx.x;
    if (t >= 4096) return;
    int c = t & 15, k = (t >> 4) & 15, m = (t >> 8) & 15;
    float acc = 0.0f;
#pragma unroll
    for (int a = 0; a < 16; a++)
        acc = fmaf(Wb[c * 256 + a * 16 + k], Wb[a * 256 + c * 16 + m], acc);
    g_T2[(m * 16 + k) * 16 + c] = acc;
}

// ---------------------------------------------------------------------------
// prep_W: split Wp2 into bf16 hi/lo (same [k][n] layout)
// ---------------------------------------------------------------------------
__global__ void prep_W_kernel(const float* __restrict__ Wp2) {
    int t = blockIdx.x * blockDim.x + threadIdx.x;   // 262144
    float w = Wp2[t];
    __nv_bfloat16 hb = __float2bfloat16(w);
    __nv_bfloat16 lb = __float2bfloat16(w - __bfloat162float(hb));
    g_Wh[t] = hb;
    g_Wl[t] = lb;
}

// ---------------------------------------------------------------------------
// zpath (known good from round 1)
// ---------------------------------------------------------------------------
__global__ __launch_bounds__(256) void zpath_kernel(
    const int*   __restrict__ xg,
    const float* __restrict__ emb,
    const float* __restrict__ W1,  const float* __restrict__ b1,
    const float* __restrict__ W2,  const float* __restrict__ b2,
    const float* __restrict__ ob,
    const float* __restrict__ Wc1, const float* __restrict__ bc1,
    const float* __restrict__ Wc2, const float* __restrict__ bc2,
    int B)
{
    __shared__ float W1s[256], W2s[256], Wc1s[256];
    __shared__ float T3s[4096];
    __shared__ float b1s[16], b2s[16], obs[16], bc1s[16], Wc2s[16];
    __shared__ float bc2s;

    int tid = threadIdx.x;
    W1s[tid]  = W1[tid];
    W2s[tid]  = W2[tid];
    Wc1s[tid] = Wc1[tid];
    for (int i = tid; i < 4096; i += 256) T3s[i] = g_T2[i];
    if (tid < 16) {
        b1s[tid] = b1[tid]; b2s[tid] = b2[tid]; obs[tid] = ob[tid];
        bc1s[tid] = bc1[tid]; Wc2s[tid] = Wc2[tid];
    }
    if (tid == 0) bc2s = bc2[0];
    __syncthreads();

    int b = blockIdx.x * 256 + tid;
    if (b >= B) return;
    int2 xi = ((const int2*)xg)[b];

    float h0[16], h1[16];
#pragma unroll
    for (int s = 0; s < 2; s++) {
        long row = (s == 0) ? (long)xi.x : (long)xi.y;
        const float4* ep = (const float4*)(emb + row * 16);
        float4 E0 = ep[0], E1 = ep[1], E2 = ep[2], E3 = ep[3];
        float e[16] = {E0.x, E0.y, E0.z, E0.w, E1.x, E1.y, E1.z, E1.w,
                       E2.x, E2.y, E2.z, E2.w, E3.x, E3.y, E3.z, E3.w};
        float t[16];
#pragma unroll
        for (int j = 0; j < 16; j++) t[j] = b1s[j];
#pragma unroll
        for (int i = 0; i < 16; i++) {
            float ei = e[i];
#pragma unroll
            for (int j = 0; j < 16; j++) t[j] = fmaf(ei, W1s[i * 16 + j], t[j]);
        }
#pragma unroll
        for (int j = 0; j < 16; j++) t[j] = fmaxf(t[j], 0.0f);
        float* h = (s == 0) ? h0 : h1;
#pragma unroll
        for (int j = 0; j < 16; j++) h[j] = b2s[j];
#pragma unroll
        for (int i = 0; i < 16; i++) {
            float ti = t[i];
#pragma unroll
            for (int j = 0; j < 16; j++) h[j] = fmaf(ti, W2s[i * 16 + j], h[j]);
        }
    }

    float z[16];
#pragma unroll
    for (int c = 0; c < 16; c++) z[c] = obs[c];
    for (int m = 0; m < 16; m++) {
        float e1m = h1[m];
        const float4* tbase = (const float4*)&T3s[(m * 16) * 16];
#pragma unroll
        for (int k2 = 0; k2 < 16; k2++) {
            float o = h0[k2] * e1m;
            float4 ta = tbase[k2 * 4 + 0];
            float4 tb = tbase[k2 * 4 + 1];
            float4 tc = tbase[k2 * 4 + 2];
            float4 td = tbase[k2 * 4 + 3];
            z[0]  = fmaf(o, ta.x, z[0]);  z[1]  = fmaf(o, ta.y, z[1]);
            z[2]  = fmaf(o, ta.z, z[2]);  z[3]  = fmaf(o, ta.w, z[3]);
            z[4]  = fmaf(o, tb.x, z[4]);  z[5]  = fmaf(o, tb.y, z[5]);
            z[6]  = fmaf(o, tb.z, z[6]);  z[7]  = fmaf(o, tb.w, z[7]);
            z[8]  = fmaf(o, tc.x, z[8]);  z[9]  = fmaf(o, tc.y, z[9]);
            z[10] = fmaf(o, tc.z, z[10]); z[11] = fmaf(o, tc.w, z[11]);
            z[12] = fmaf(o, td.x, z[12]); z[13] = fmaf(o, td.y, z[13]);
            z[14] = fmaf(o, td.z, z[14]); z[15] = fmaf(o, td.w, z[15]);
        }
    }

    float zz = bc2s;
#pragma unroll
    for (int j = 0; j < 16; j++) {
        float a = bc1s[j];
#pragma unroll
        for (int c = 0; c < 16; c++) a = fmaf(z[c], Wc1s[c * 16 + j], a);
        a = fmaxf(a, 0.0f);
        zz = fmaf(a, Wc2s[j], zz);
    }
    g_zbuf[b] = zz;
}

// ---------------------------------------------------------------------------
// gemm_mma: C = g1 @ Wp2 via split-bf16 3-pass mma.sync, fused epilogue.
// CTA: 64 rows x 512 cols, 256 threads = 8 warps (2m x 4n), warp tile 32x128.
// K: 16 chunks of 32, 2-stage cp.async pipeline.
//
// SMEM map (bytes):
//   B tiles: [2 stage][2 mat][32 k][512 n] bf16, row k = 1024B, XOR-swizzled
//            within 128B: off = k*1024 + ((n*2) ^ ((k&7)*16))
//   A tiles: [2 stage][2 mat][64 m][80B row] (40 bf16, 32 used; stride 80 is
//            conflict-free for ldmatrix since 5*m mod 8 is a permutation)
// ---------------------------------------------------------------------------
#define OFF_B    0
#define B_STAGE  65536
#define B_MAT    32768
#define OFF_A    131072
#define A_STAGE  10240
#define A_MAT    5120
#define OFF_WP1  151552
#define OFF_WP3  155648
#define OFF_PH   157696
#define OFF_RED  158208
#define SMEM_SZ  159232

__global__ __launch_bounds__(256, 1) void gemm_mma_kernel(
    const float* __restrict__ phenos,
    const float* __restrict__ Wp1,
    const float* __restrict__ Wp3,
    const float* __restrict__ bp3,
    float* __restrict__ out,
    int B)
{
    extern __shared__ __align__(1024) unsigned char smem[];
    const uint32_t sb = smem_u32(smem);
    const int tid  = threadIdx.x;
    const int wid  = tid >> 5;
    const int lane = tid & 31;
    const int wm   = wid >> 2;          // 0..1 (m)
    const int wn   = wid & 3;           // 0..3 (n)
    const int rowbase = blockIdx.x * 64;

    float*  wp1s = (float*)(smem + OFF_WP1);
    float*  wp3s = (float*)(smem + OFF_WP3);
    float2* ph2  = (float2*)(smem + OFF_PH);
    float*  red  = (float*)(smem + OFF_RED);

    for (int i = tid; i < 1024; i += 256) wp1s[i] = Wp1[i];
    for (int i = tid; i < 512;  i += 256) wp3s[i] = Wp3[i];
    if (tid < 64) {
        int b = rowbase + tid;
        ph2[tid] = (b < B) ? ((const float2*)phenos)[b] : make_float2(0.f, 0.f);
    }
    __syncthreads();

    // ---- per-thread producer constants ----
    const int pm = tid & 63;            // row this thread produces g1 for
    const int pk = tid >> 6;            // k-block (0..3) -> k = pk*8..pk*8+7
    const float2 php = ph2[pm];

    // ---- per-lane ldmatrix address components ----
    const int g        = lane >> 3;
    const int rin16    = ((g & 1) << 3) + (lane & 7);       // row within 16
    const int a_lane   = rin16 * 80 + ((g >> 1) << 4);      // A frag lane off
    const int b_krow   = rin16;                             // B k row within 16
    const int b_swz    = (b_krow & 7) << 4;
    const int b_colb   = (wn * 256) + ((g >> 1) << 4);      // byte col base

    // producer lambda: fill stage s with chunk c
    auto produce = [&](int c, int s) {
        // B tiles via cp.async (16 granules per thread)
        const uint32_t bdst = sb + OFF_B + s * B_STAGE;
#pragma unroll
        for (int i = 0; i < 16; i++) {
            int idx = tid + i * 256;          // 0..4095
            int mat = idx >> 11;
            int rem = idx & 2047;
            int k   = rem >> 6;
            int u   = rem & 63;
            const __nv_bfloat16* src =
                (mat == 0 ? g_Wh : g_Wl) + (c * 32 + k) * 512 + u * 8;
            uint32_t dst = bdst + mat * B_MAT + k * 1024 +
                           (((uint32_t)(u * 16)) ^ ((uint32_t)((k & 7) * 16)));
            CP_ASYNC16(dst, (const void*)src);
        }
        CP_COMMIT();
        // A tile: gelu(phenos @ Wp1) -> split bf16 hi/lo
        uint32_t hw[4], lw[4];
#pragma unroll
        for (int j = 0; j < 4; j++) {
            int k0 = c * 32 + pk * 8 + j * 2;
            float x0 = fmaf(php.y, wp1s[512 + k0],     php.x * wp1s[k0]);
            float x1 = fmaf(php.y, wp1s[512 + k0 + 1], php.x * wp1s[k0 + 1]);
            float g0 = gelu_fast(x0), g1v = gelu_fast(x1);
            __nv_bfloat16 h0 = __float2bfloat16(g0);
            __nv_bfloat16 h1 = __float2bfloat16(g1v);
            __nv_bfloat16 l0 = __float2bfloat16(g0 - __bfloat162float(h0));
            __nv_bfloat16 l1 = __float2bfloat16(g1v - __bfloat162float(h1));
            hw[j] = (uint32_t)__bfloat16_as_ushort(h0) |
                    ((uint32_t)__bfloat16_as_ushort(h1) << 16);
            lw[j] = (uint32_t)__bfloat16_as_ushort(l0) |
                    ((uint32_t)__bfloat16_as_ushort(l1) << 16);
        }
        uint32_t adst = sb + OFF_A + s * A_STAGE + pm * 80 + pk * 16;
        asm volatile("st.shared.v4.b32 [%0], {%1,%2,%3,%4};"
                     :: "r"(adst), "r"(hw[0]), "r"(hw[1]), "r"(hw[2]), "r"(hw[3])
                     : "memory");
        asm volatile("st.shared.v4.b32 [%0], {%1,%2,%3,%4};"
                     :: "r"(adst + A_MAT), "r"(lw[0]), "r"(lw[1]), "r"(lw[2]), "r"(lw[3])
                     : "memory");
    };

    float acc[2][16][4];
#pragma unroll
    for (int mt = 0; mt < 2; mt++)
#pragma unroll
        for (int n = 0; n < 16; n++)
#pragma unroll
            for (int r = 0; r < 4; r++) acc[mt][n][r] = 0.0f;

    produce(0, 0);

    for (int c = 0; c < 16; c++) {
        const int buf = c & 1;
        if (c + 1 < 16) produce(c + 1, buf ^ 1);
        else            CP_COMMIT();
        CP_WAIT1();
        __syncthreads();

        const uint32_t abase = sb + OFF_A + buf * A_STAGE +
                               (wm * 32) * 80 + a_lane;
        const uint32_t bbase = sb + OFF_B + buf * B_STAGE + b_krow * 1024;

#pragma unroll
        for (int ks = 0; ks < 2; ks++) {
            // load A fragments (hi, lo) for 2 m-tiles
            uint32_t ah[2][4], al[2][4];
#pragma unroll
            for (int mt = 0; mt < 2; mt++) {
                uint32_t aa = abase + mt * 1280 + ks * 32;
                LDMX4(ah[mt][0], ah[mt][1], ah[mt][2], ah[mt][3], aa);
                LDMX4(al[mt][0], al[mt][1], al[mt][2], al[mt][3], aa + A_MAT);
            }
            // load B fragments (hi, lo) for 16 n-tiles (8 ldmatrix each)
            uint32_t bh[16][2], bl[16][2];
#pragma unroll
            for (int np = 0; np < 8; np++) {
                uint32_t coff = (uint32_t)((b_colb + np * 32)) ^ (uint32_t)b_swz;
                uint32_t ba = bbase + ks * 16384 + coff;
                LDMX4T(bh[np * 2][0], bh[np * 2][1],
                       bh[np * 2 + 1][0], bh[np * 2 + 1][1], ba);
                LDMX4T(bl[np * 2][0], bl[np * 2][1],
                       bl[np * 2 + 1][0], bl[np * 2 + 1][1], ba + B_MAT);
            }
            // 3 passes: Ah*Wh, Ah*Wl, Al*Wh
#pragma unroll
            for (int n = 0; n < 16; n++)
#pragma unroll
                for (int mt = 0; mt < 2; mt++)
                    MMA16816(acc[mt][n], ah[mt], bh[n]);
#pragma unroll
            for (int n = 0; n < 16; n++)
#pragma unroll
                for (int mt = 0; mt < 2; mt++)
                    MMA16816(acc[mt][n], ah[mt], bl[n]);
#pragma unroll
            for (int n = 0; n < 16; n++)
#pragma unroll
                for (int mt = 0; mt < 2; mt++)
                    MMA16816(acc[mt][n], al[mt], bh[n]);
        }
        __syncthreads();
    }

    // ---- epilogue: gelu(C) @ Wp3, deterministic reduce, + z + bp3 ----
    const int q   = lane >> 2;
    const int idq = lane & 3;
    float p4[4] = {0.f, 0.f, 0.f, 0.f};
#pragma unroll
    for (int mt = 0; mt < 2; mt++)
#pragma unroll
        for (int n = 0; n < 16; n++)
#pragma unroll
            for (int r = 0; r < 4; r++) {
                int col = wn * 128 + n * 8 + idq * 2 + (r & 1);
                float v = gelu_fast(acc[mt][n][r]) * wp3s[col];
                p4[mt * 2 + (r >> 1)] += v;
            }
#pragma unroll
    for (int i = 0; i < 4; i++) {
        float s = p4[i];
        s += __shfl_xor_sync(0xFFFFFFFF, s, 1);
        s += __shfl_xor_sync(0xFFFFFFFF, s, 2);
        if (idq == 0) {
            int row = wm * 32 + (i >> 1) * 16 + (i & 1) * 8 + q;
            red[row * 4 + wn] = s;
        }
    }
    __syncthreads();
    if (tid < 64) {
        int b = rowbase + tid;
        if (b < B) {
            float s = red[tid * 4] + red[tid * 4 + 1] +
                      red[tid * 4 + 2] + red[tid * 4 + 3];
            out[b] = g_zbuf[b] + s + bp3[0];
        }
    }
}

// ---------------------------------------------------------------------------
// Launch
// ---------------------------------------------------------------------------
extern "C" void kernel_launch(void* const* d_in, const int* in_sizes, int n_in,
                              void* d_out, int out_size) {
    const int*   x      = (const int*)  d_in[0];
    const float* phenos = (const float*)d_in[1];
    const float* emb    = (const float*)d_in[2];
    const float* W1     = (const float*)d_in[3];
    const float* b1     = (const float*)d_in[4];
    const float* W2     = (const float*)d_in[5];
    const float* b2     = (const float*)d_in[6];
    const float* Wb     = (const float*)d_in[7];
    const float* ob     = (const float*)d_in[8];
    const float* Wc1    = (const float*)d_in[9];
    const float* bc1    = (const float*)d_in[10];
    const float* Wc2    = (const float*)d_in[11];
    const float* bc2    = (const float*)d_in[12];
    const float* Wp1    = (const float*)d_in[13];
    const float* Wp2    = (const float*)d_in[14];
    const float* Wp3    = (const float*)d_in[15];
    const float* bp3    = (const float*)d_in[16];
    float* out = (float*)d_out;

    int B = in_sizes[0] / 2;

    cudaFuncSetAttribute(gemm_mma_kernel,
                         cudaFuncAttributeMaxDynamicSharedMemorySize, SMEM_SZ);

    prep_T_kernel<<<16, 256>>>(Wb);
    prep_W_kernel<<<1024, 256>>>(Wp2);
    zpath_kernel<<<(B + 255) / 256, 256>>>(x, emb, W1, b1, W2, b2, ob,
                                           Wc1, bc1, Wc2, bc2, B);
    gemm_mma_kernel<<<(B + 63) / 64, 256, SMEM_SZ>>>(phenos, Wp1, Wp3, bp3,
                                                     out, B);
}

// round 4
// speedup vs baseline: 2.3765x; 1.0263x over previous
#include <cuda_runtime.h>
#include <cuda_bf16.h>
#include <math.h>
#include <stdint.h>

// ---------------------------------------------------------------------------
// Device scratch (declared statically; no dynamic allocation)
// ---------------------------------------------------------------------------
__device__ float g_T2[4096];                    // folded bilinear tensor
__device__ float g_zbuf[1 << 17];               // per-row z scalar
__device__ __nv_bfloat16 g_Wh[512 * 512];       // Wp2 split hi (layout [k][n])
__device__ __nv_bfloat16 g_Wl[512 * 512];       // Wp2 split lo (layout [k][n])

// ---------------------------------------------------------------------------
// Helpers
// ---------------------------------------------------------------------------
__device__ __forceinline__ uint32_t smem_u32(const void* p) {
    uint32_t a;
    asm("{ .reg .u64 t; cvta.to.shared.u64 t, %1; cvt.u32.u64 %0, t; }"
        : "=r"(a) : "l"(p));
    return a;
}

// Branch-free gelu, exact-erf via Abramowitz-Stegun 7.1.26 (|err| <= 1.5e-7)
__device__ __forceinline__ float gelu_fast(float x) {
    float ax = fabsf(x);
    float z  = ax * 0.70710678118654752440f;
    float t  = __fdividef(1.0f, fmaf(0.3275911f, z, 1.0f));
    float e  = __expf(-z * z);
    float y  = fmaf(t, 1.061405429f, -1.453152027f);
    y = fmaf(y, t, 1.421413741f);
    y = fmaf(y, t, -0.284496736f);
    y = fmaf(y, t, 0.254829592f);
    y = y * t * e;                       // 1 - erf(z)
    float erfv = 1.0f - y;               // erf(|x|/sqrt(2))
    return 0.5f * fmaf(ax, erfv, x);
}

#define LDMX4(r0, r1, r2, r3, a)                                              \
    asm volatile("ldmatrix.sync.aligned.m8n8.x4.shared.b16 {%0,%1,%2,%3}, [%4];" \
                 : "=r"(r0), "=r"(r1), "=r"(r2), "=r"(r3) : "r"(a))

#define LDMX4T(r0, r1, r2, r3, a)                                             \
    asm volatile("ldmatrix.sync.aligned.m8n8.x4.trans.shared.b16 {%0,%1,%2,%3}, [%4];" \
                 : "=r"(r0), "=r"(r1), "=r"(r2), "=r"(r3) : "r"(a))

#define MMA16816(d, a, b)                                                     \
    asm("mma.sync.aligned.m16n8k16.row.col.f32.bf16.bf16.f32 "               \
        "{%0,%1,%2,%3}, {%4,%5,%6,%7}, {%8,%9}, {%0,%1,%2,%3};"               \
        : "+f"((d)[0]), "+f"((d)[1]), "+f"((d)[2]), "+f"((d)[3])              \
        : "r"((a)[0]), "r"((a)[1]), "r"((a)[2]), "r"((a)[3]),                 \
          "r"((b)[0]), "r"((b)[1]))

#define CP_ASYNC16(dst, src)                                                  \
    asm volatile("cp.async.cg.shared.global [%0], [%1], 16;"                  \
                 :: "r"(dst), "l"(src) : "memory")

#define CP_COMMIT() asm volatile("cp.async.commit_group;" ::: "memory")
#define CP_WAIT1()  asm volatile("cp.async.wait_group 1;" ::: "memory")

// ---------------------------------------------------------------------------
// prep_T: T[c,k,m] = sum_a Wb[c,a,k]*Wb[a,c,m]
// ---------------------------------------------------------------------------
__global__ void prep_T_kernel(const float* __restrict__ Wb) {
    int t = blockIdx.x * blockDim.x + threadIdx.x;
    if (t >= 4096) return;
    int c = t & 15, k = (t >> 4) & 15, m = (t >> 8) & 15;
    float acc = 0.0f;
#pragma unroll
    for (int a = 0; a < 16; a++)
        acc = fmaf(Wb[c * 256 + a * 16 + k], Wb[a * 256 + c * 16 + m], acc);
    g_T2[(m * 16 + k) * 16 + c] = acc;
}

// ---------------------------------------------------------------------------
// prep_W: split Wp2 into bf16 hi/lo (same [k][n] layout)
// ---------------------------------------------------------------------------
__global__ void prep_W_kernel(const float* __restrict__ Wp2) {
    int t = blockIdx.x * blockDim.x + threadIdx.x;   // 262144
    float w = Wp2[t];
    __nv_bfloat16 hb = __float2bfloat16(w);
    __nv_bfloat16 lb = __float2bfloat16(w - __bfloat162float(hb));
    g_Wh[t] = hb;
    g_Wl[t] = lb;
}

// ---------------------------------------------------------------------------
// zpath (known good)
// ---------------------------------------------------------------------------
__global__ __launch_bounds__(256) void zpath_kernel(
    const int*   __restrict__ xg,
    const float* __restrict__ emb,
    const float* __restrict__ W1,  const float* __restrict__ b1,
    const float* __restrict__ W2,  const float* __restrict__ b2,
    const float* __restrict__ ob,
    const float* __restrict__ Wc1, const float* __restrict__ bc1,
    const float* __restrict__ Wc2, const float* __restrict__ bc2,
    int B)
{
    __shared__ float W1s[256], W2s[256], Wc1s[256];
    __shared__ float T3s[4096];
    __shared__ float b1s[16], b2s[16], obs[16], bc1s[16], Wc2s[16];
    __shared__ float bc2s;

    int tid = threadIdx.x;
    W1s[tid]  = W1[tid];
    W2s[tid]  = W2[tid];
    Wc1s[tid] = Wc1[tid];
    for (int i = tid; i < 4096; i += 256) T3s[i] = g_T2[i];
    if (tid < 16) {
        b1s[tid] = b1[tid]; b2s[tid] = b2[tid]; obs[tid] = ob[tid];
        bc1s[tid] = bc1[tid]; Wc2s[tid] = Wc2[tid];
    }
    if (tid == 0) bc2s = bc2[0];
    __syncthreads();

    int b = blockIdx.x * 256 + tid;
    if (b >= B) return;
    int2 xi = ((const int2*)xg)[b];

    float h0[16], h1[16];
#pragma unroll
    for (int s = 0; s < 2; s++) {
        long row = (s == 0) ? (long)xi.x : (long)xi.y;
        const float4* ep = (const float4*)(emb + row * 16);
        float4 E0 = ep[0], E1 = ep[1], E2 = ep[2], E3 = ep[3];
        float e[16] = {E0.x, E0.y, E0.z, E0.w, E1.x, E1.y, E1.z, E1.w,
                       E2.x, E2.y, E2.z, E2.w, E3.x, E3.y, E3.z, E3.w};
        float t[16];
#pragma unroll
        for (int j = 0; j < 16; j++) t[j] = b1s[j];
#pragma unroll
        for (int i = 0; i < 16; i++) {
            float ei = e[i];
#pragma unroll
            for (int j = 0; j < 16; j++) t[j] = fmaf(ei, W1s[i * 16 + j], t[j]);
        }
#pragma unroll
        for (int j = 0; j < 16; j++) t[j] = fmaxf(t[j], 0.0f);
        float* h = (s == 0) ? h0 : h1;
#pragma unroll
        for (int j = 0; j < 16; j++) h[j] = b2s[j];
#pragma unroll
        for (int i = 0; i < 16; i++) {
            float ti = t[i];
#pragma unroll
            for (int j = 0; j < 16; j++) h[j] = fmaf(ti, W2s[i * 16 + j], h[j]);
        }
    }

    float z[16];
#pragma unroll
    for (int c = 0; c < 16; c++) z[c] = obs[c];
    for (int m = 0; m < 16; m++) {
        float e1m = h1[m];
        const float4* tbase = (const float4*)&T3s[(m * 16) * 16];
#pragma unroll
        for (int k2 = 0; k2 < 16; k2++) {
            float o = h0[k2] * e1m;
            float4 ta = tbase[k2 * 4 + 0];
            float4 tb = tbase[k2 * 4 + 1];
            float4 tc = tbase[k2 * 4 + 2];
            float4 td = tbase[k2 * 4 + 3];
            z[0]  = fmaf(o, ta.x, z[0]);  z[1]  = fmaf(o, ta.y, z[1]);
            z[2]  = fmaf(o, ta.z, z[2]);  z[3]  = fmaf(o, ta.w, z[3]);
            z[4]  = fmaf(o, tb.x, z[4]);  z[5]  = fmaf(o, tb.y, z[5]);
            z[6]  = fmaf(o, tb.z, z[6]);  z[7]  = fmaf(o, tb.w, z[7]);
            z[8]  = fmaf(o, tc.x, z[8]);  z[9]  = fmaf(o, tc.y, z[9]);
            z[10] = fmaf(o, tc.z, z[10]); z[11] = fmaf(o, tc.w, z[11]);
            z[12] = fmaf(o, td.x, z[12]); z[13] = fmaf(o, td.y, z[13]);
            z[14] = fmaf(o, td.z, z[14]); z[15] = fmaf(o, td.w, z[15]);
        }
    }

    float zz = bc2s;
#pragma unroll
    for (int j = 0; j < 16; j++) {
        float a = bc1s[j];
#pragma unroll
        for (int c = 0; c < 16; c++) a = fmaf(z[c], Wc1s[c * 16 + j], a);
        a = fmaxf(a, 0.0f);
        zz = fmaf(a, Wc2s[j], zz);
    }
    g_zbuf[b] = zz;
}

// ---------------------------------------------------------------------------
// gemm_mma: C = g1 @ Wp2 via split-bf16 3-pass mma.sync, fused epilogue.
// CTA: 64 rows x 512 cols, 512 threads = 16 warps (4m x 4n), warp tile 16x128.
// K: 16 chunks of 32, 2-stage cp.async pipeline. B fragments loaded JIT in
// blocks of 4 n-tiles to keep live registers ~110 (no spills, 128-reg cap).
// ---------------------------------------------------------------------------
#define OFF_B    0
#define B_STAGE  65536
#define B_MAT    32768
#define OFF_A    131072
#define A_STAGE  10240
#define A_MAT    5120
#define OFF_WP1  151552
#define OFF_WP3  155648
#define OFF_PH   157696
#define OFF_RED  158208
#define SMEM_SZ  159232

__global__ __launch_bounds__(512, 1) void gemm_mma_kernel(
    const float* __restrict__ phenos,
    const float* __restrict__ Wp1,
    const float* __restrict__ Wp3,
    const float* __restrict__ bp3,
    float* __restrict__ out,
    int B)
{
    extern __shared__ __align__(1024) unsigned char smem[];
    const uint32_t sb = smem_u32(smem);
    const int tid  = threadIdx.x;
    const int wid  = tid >> 5;
    const int lane = tid & 31;
    const int wm   = wid >> 2;          // 0..3 (m)
    const int wn   = wid & 3;           // 0..3 (n)
    const int rowbase = blockIdx.x * 64;

    float*  wp1s = (float*)(smem + OFF_WP1);
    float*  wp3s = (float*)(smem + OFF_WP3);
    float2* ph2  = (float2*)(smem + OFF_PH);
    float*  red  = (float*)(smem + OFF_RED);

    for (int i = tid; i < 1024; i += 512) wp1s[i] = Wp1[i];
    if (tid < 512) wp3s[tid] = Wp3[tid];
    if (tid < 64) {
        int b = rowbase + tid;
        ph2[tid] = (b < B) ? ((const float2*)phenos)[b] : make_float2(0.f, 0.f);
    }
    __syncthreads();

    // ---- producer constants: A row pm, k-subblock pk (4 k each) ----
    const int pm = tid & 63;
    const int pk = tid >> 6;            // 0..7
    const float2 php = ph2[pm];

    // ---- ldmatrix lane address components ----
    const int g      = lane >> 3;
    const int rin16  = ((g & 1) << 3) + (lane & 7);
    const int a_lane = rin16 * 80 + ((g >> 1) << 4);
    const int b_krow = rin16;
    const int b_swz  = (b_krow & 7) << 4;
    const int b_colb = (wn * 256) + ((g >> 1) << 4);

    auto produce = [&](int c, int s) {
        // B tiles via cp.async (8 granules of 16B per thread)
        const uint32_t bdst = sb + OFF_B + s * B_STAGE;
#pragma unroll
        for (int i = 0; i < 8; i++) {
            int idx = tid + i * 512;          // 0..4095
            int mat = idx >> 11;
            int rem = idx & 2047;
            int k   = rem >> 6;
            int u   = rem & 63;
            const __nv_bfloat16* src =
                (mat == 0 ? g_Wh : g_Wl) + (c * 32 + k) * 512 + u * 8;
            uint32_t dst = bdst + mat * B_MAT + k * 1024 +
                           (((uint32_t)(u * 16)) ^ ((uint32_t)((k & 7) * 16)));
            CP_ASYNC16(dst, (const void*)src);
        }
        CP_COMMIT();
        // A tile: gelu(phenos @ Wp1), split bf16 hi/lo — 4 k per thread
        uint32_t hw[2], lw[2];
#pragma unroll
        for (int j = 0; j < 2; j++) {
            int k0 = c * 32 + pk * 4 + j * 2;
            float x0 = fmaf(php.y, wp1s[512 + k0],     php.x * wp1s[k0]);
            float x1 = fmaf(php.y, wp1s[512 + k0 + 1], php.x * wp1s[k0 + 1]);
            float g0 = gelu_fast(x0), g1v = gelu_fast(x1);
            __nv_bfloat16 h0 = __float2bfloat16(g0);
            __nv_bfloat16 h1 = __float2bfloat16(g1v);
            __nv_bfloat16 l0 = __float2bfloat16(g0 - __bfloat162float(h0));
            __nv_bfloat16 l1 = __float2bfloat16(g1v - __bfloat162float(h1));
            hw[j] = (uint32_t)__bfloat16_as_ushort(h0) |
                    ((uint32_t)__bfloat16_as_ushort(h1) << 16);
            lw[j] = (uint32_t)__bfloat16_as_ushort(l0) |
                    ((uint32_t)__bfloat16_as_ushort(l1) << 16);
        }
        uint32_t adst = sb + OFF_A + s * A_STAGE + pm * 80 + pk * 8;
        asm volatile("st.shared.v2.b32 [%0], {%1,%2};"
                     :: "r"(adst), "r"(hw[0]), "r"(hw[1]) : "memory");
        asm volatile("st.shared.v2.b32 [%0], {%1,%2};"
                     :: "r"(adst + A_MAT), "r"(lw[0]), "r"(lw[1]) : "memory");
    };

    float acc[16][4];
#pragma unroll
    for (int n = 0; n < 16; n++)
#pragma unroll
        for (int r = 0; r < 4; r++) acc[n][r] = 0.0f;

    produce(0, 0);

    for (int c = 0; c < 16; c++) {
        const int buf = c & 1;
        if (c + 1 < 16) produce(c + 1, buf ^ 1);
        else            CP_COMMIT();
        CP_WAIT1();
        __syncthreads();

        const uint32_t abase = sb + OFF_A + buf * A_STAGE + (wm * 16) * 80 + a_lane;
        const uint32_t bbase = sb + OFF_B + buf * B_STAGE + b_krow * 1024;

#pragma unroll
        for (int ks = 0; ks < 2; ks++) {
            uint32_t ah[4], al[4];
            uint32_t aa = abase + ks * 32;
            LDMX4(ah[0], ah[1], ah[2], ah[3], aa);
            LDMX4(al[0], al[1], al[2], al[3], aa + A_MAT);

#pragma unroll
            for (int nb = 0; nb < 4; nb++) {
                uint32_t bh[4][2], bl[4][2];
#pragma unroll
                for (int hp = 0; hp < 2; hp++) {
                    uint32_t coff = (uint32_t)(b_colb + (nb * 2 + hp) * 32) ^
                                    (uint32_t)b_swz;
                    uint32_t ba = bbase + ks * 16384 + coff;
                    LDMX4T(bh[hp * 2][0], bh[hp * 2][1],
                           bh[hp * 2 + 1][0], bh[hp * 2 + 1][1], ba);
                    LDMX4T(bl[hp * 2][0], bl[hp * 2][1],
                           bl[hp * 2 + 1][0], bl[hp * 2 + 1][1], ba + B_MAT);
                }
#pragma unroll
                for (int j = 0; j < 4; j++) MMA16816(acc[nb * 4 + j], ah, bh[j]);
#pragma unroll
                for (int j = 0; j < 4; j++) MMA16816(acc[nb * 4 + j], ah, bl[j]);
#pragma unroll
                for (int j = 0; j < 4; j++) MMA16816(acc[nb * 4 + j], al, bh[j]);
            }
        }
        __syncthreads();
    }

    // ---- epilogue: gelu(C) @ Wp3, deterministic reduce, + z + bp3 ----
    const int q   = lane >> 2;
    const int idq = lane & 3;
    float p2[2] = {0.f, 0.f};
#pragma unroll
    for (int n = 0; n < 16; n++)
#pragma unroll
        for (int r = 0; r < 4; r++) {
            int col = wn * 128 + n * 8 + idq * 2 + (r & 1);
            p2[r >> 1] = fmaf(gelu_fast(acc[n][r]), wp3s[col], p2[r >> 1]);
        }
#pragma unroll
    for (int i = 0; i < 2; i++) {
        float s = p2[i];
        s += __shfl_xor_sync(0xFFFFFFFF, s, 1);
        s += __shfl_xor_sync(0xFFFFFFFF, s, 2);
        if (idq == 0) {
            int row = wm * 16 + i * 8 + q;
            red[row * 4 + wn] = s;
        }
    }
    __syncthreads();
    if (tid < 64) {
        int b = rowbase + tid;
        if (b < B) {
            float s = red[tid * 4] + red[tid * 4 + 1] +
                      red[tid * 4 + 2] + red[tid * 4 + 3];
            out[b] = g_zbuf[b] + s + bp3[0];
        }
    }
}

// ---------------------------------------------------------------------------
// Launch
// ---------------------------------------------------------------------------
extern "C" void kernel_launch(void* const* d_in, const int* in_sizes, int n_in,
                              void* d_out, int out_size) {
    const int*   x      = (const int*)  d_in[0];
    const float* phenos = (const float*)d_in[1];
    const float* emb    = (const float*)d_in[2];
    const float* W1     = (const float*)d_in[3];
    const float* b1     = (const float*)d_in[4];
    const float* W2     = (const float*)d_in[5];
    const float* b2     = (const float*)d_in[6];
    const float* Wb     = (const float*)d_in[7];
    const float* ob     = (const float*)d_in[8];
    const float* Wc1    = (const float*)d_in[9];
    const float* bc1    = (const float*)d_in[10];
    const float* Wc2    = (const float*)d_in[11];
    const float* bc2    = (const float*)d_in[12];
    const float* Wp1    = (const float*)d_in[13];
    const float* Wp2    = (const float*)d_in[14];
    const float* Wp3    = (const float*)d_in[15];
    const float* bp3    = (const float*)d_in[16];
    float* out = (float*)d_out;

    int B = in_sizes[0] / 2;

    cudaFuncSetAttribute(gemm_mma_kernel,
                         cudaFuncAttributeMaxDynamicSharedMemorySize, SMEM_SZ);

    prep_T_kernel<<<16, 256>>>(Wb);
    prep_W_kernel<<<1024, 256>>>(Wp2);
    zpath_kernel<<<(B + 255) / 256, 256>>>(x, emb, W1, b1, W2, b2, ob,
                                           Wc1, bc1, Wc2, bc2, B);
    gemm_mma_kernel<<<(B + 63) / 64, 512, SMEM_SZ>>>(phenos, Wp1, Wp3, bp3,
                                                     out, B);
}

// round 5
// speedup vs baseline: 2.4956x; 1.0501x over previous
#include <cuda_runtime.h>
#include <cuda_bf16.h>
#include <math.h>
#include <stdint.h>

// ---------------------------------------------------------------------------
// Device scratch (declared statically; no dynamic allocation)
// ---------------------------------------------------------------------------
__device__ float g_T2[4096];                    // folded bilinear tensor
__device__ float g_zbuf[1 << 17];               // per-row z scalar
__device__ __nv_bfloat16 g_Wh[512 * 512];       // Wp2 split hi (layout [k][n])
__device__ __nv_bfloat16 g_Wl[512 * 512];       // Wp2 split lo (layout [k][n])

// ---------------------------------------------------------------------------
// Helpers
// ---------------------------------------------------------------------------
__device__ __forceinline__ uint32_t smem_u32(const void* p) {
    uint32_t a;
    asm("{ .reg .u64 t; cvta.to.shared.u64 t, %1; cvt.u32.u64 %0, t; }"
        : "=r"(a) : "l"(p));
    return a;
}

// Branch-free gelu, exact-erf via Abramowitz-Stegun 7.1.26 (|err| <= 1.5e-7)
__device__ __forceinline__ float gelu_fast(float x) {
    float ax = fabsf(x);
    float z  = ax * 0.70710678118654752440f;
    float t  = __fdividef(1.0f, fmaf(0.3275911f, z, 1.0f));
    float e  = __expf(-z * z);
    float y  = fmaf(t, 1.061405429f, -1.453152027f);
    y = fmaf(y, t, 1.421413741f);
    y = fmaf(y, t, -0.284496736f);
    y = fmaf(y, t, 0.254829592f);
    y = y * t * e;                       // 1 - erf(z)
    float erfv = 1.0f - y;               // erf(|x|/sqrt(2))
    return 0.5f * fmaf(ax, erfv, x);
}

#define LDMX4(r0, r1, r2, r3, a)                                              \
    asm volatile("ldmatrix.sync.aligned.m8n8.x4.shared.b16 {%0,%1,%2,%3}, [%4];" \
                 : "=r"(r0), "=r"(r1), "=r"(r2), "=r"(r3) : "r"(a))

#define LDMX4T(r0, r1, r2, r3, a)                                             \
    asm volatile("ldmatrix.sync.aligned.m8n8.x4.trans.shared.b16 {%0,%1,%2,%3}, [%4];" \
                 : "=r"(r0), "=r"(r1), "=r"(r2), "=r"(r3) : "r"(a))

#define MMA16816(d, a, b)                                                     \
    asm("mma.sync.aligned.m16n8k16.row.col.f32.bf16.bf16.f32 "               \
        "{%0,%1,%2,%3}, {%4,%5,%6,%7}, {%8,%9}, {%0,%1,%2,%3};"               \
        : "+f"((d)[0]), "+f"((d)[1]), "+f"((d)[2]), "+f"((d)[3])              \
        : "r"((a)[0]), "r"((a)[1]), "r"((a)[2]), "r"((a)[3]),                 \
          "r"((b)[0]), "r"((b)[1]))

#define CP_ASYNC16(dst, src)                                                  \
    asm volatile("cp.async.cg.shared.global [%0], [%1], 16;"                  \
                 :: "r"(dst), "l"(src) : "memory")

#define CP_COMMIT() asm volatile("cp.async.commit_group;" ::: "memory")
#define CP_WAIT1()  asm volatile("cp.async.wait_group 1;" ::: "memory")

// ---------------------------------------------------------------------------
// prep_T: T[c,k,m] = sum_a Wb[c,a,k]*Wb[a,c,m]
// ---------------------------------------------------------------------------
__global__ void prep_T_kernel(const float* __restrict__ Wb) {
    int t = blockIdx.x * blockDim.x + threadIdx.x;
    if (t >= 4096) return;
    int c = t & 15, k = (t >> 4) & 15, m = (t >> 8) & 15;
    float acc = 0.0f;
#pragma unroll
    for (int a = 0; a < 16; a++)
        acc = fmaf(Wb[c * 256 + a * 16 + k], Wb[a * 256 + c * 16 + m], acc);
    g_T2[(m * 16 + k) * 16 + c] = acc;
}

// ---------------------------------------------------------------------------
// prep_W: split Wp2 into bf16 hi/lo (same [k][n] layout)
// ---------------------------------------------------------------------------
__global__ void prep_W_kernel(const float* __restrict__ Wp2) {
    int t = blockIdx.x * blockDim.x + threadIdx.x;   // 262144
    float w = Wp2[t];
    __nv_bfloat16 hb = __float2bfloat16(w);
    __nv_bfloat16 lb = __float2bfloat16(w - __bfloat162float(hb));
    g_Wh[t] = hb;
    g_Wl[t] = lb;
}

// ---------------------------------------------------------------------------
// zpath (known good)
// ---------------------------------------------------------------------------
__global__ __launch_bounds__(256) void zpath_kernel(
    const int*   __restrict__ xg,
    const float* __restrict__ emb,
    const float* __restrict__ W1,  const float* __restrict__ b1,
    const float* __restrict__ W2,  const float* __restrict__ b2,
    const float* __restrict__ ob,
    const float* __restrict__ Wc1, const float* __restrict__ bc1,
    const float* __restrict__ Wc2, const float* __restrict__ bc2,
    int B)
{
    __shared__ float W1s[256], W2s[256], Wc1s[256];
    __shared__ float T3s[4096];
    __shared__ float b1s[16], b2s[16], obs[16], bc1s[16], Wc2s[16];
    __shared__ float bc2s;

    int tid = threadIdx.x;
    W1s[tid]  = W1[tid];
    W2s[tid]  = W2[tid];
    Wc1s[tid] = Wc1[tid];
    for (int i = tid; i < 4096; i += 256) T3s[i] = g_T2[i];
    if (tid < 16) {
        b1s[tid] = b1[tid]; b2s[tid] = b2[tid]; obs[tid] = ob[tid];
        bc1s[tid] = bc1[tid]; Wc2s[tid] = Wc2[tid];
    }
    if (tid == 0) bc2s = bc2[0];
    __syncthreads();

    int b = blockIdx.x * 256 + tid;
    if (b >= B) return;
    int2 xi = ((const int2*)xg)[b];

    float h0[16], h1[16];
#pragma unroll
    for (int s = 0; s < 2; s++) {
        long row = (s == 0) ? (long)xi.x : (long)xi.y;
        const float4* ep = (const float4*)(emb + row * 16);
        float4 E0 = ep[0], E1 = ep[1], E2 = ep[2], E3 = ep[3];
        float e[16] = {E0.x, E0.y, E0.z, E0.w, E1.x, E1.y, E1.z, E1.w,
                       E2.x, E2.y, E2.z, E2.w, E3.x, E3.y, E3.z, E3.w};
        float t[16];
#pragma unroll
        for (int j = 0; j < 16; j++) t[j] = b1s[j];
#pragma unroll
        for (int i = 0; i < 16; i++) {
            float ei = e[i];
#pragma unroll
            for (int j = 0; j < 16; j++) t[j] = fmaf(ei, W1s[i * 16 + j], t[j]);
        }
#pragma unroll
        for (int j = 0; j < 16; j++) t[j] = fmaxf(t[j], 0.0f);
        float* h = (s == 0) ? h0 : h1;
#pragma unroll
        for (int j = 0; j < 16; j++) h[j] = b2s[j];
#pragma unroll
        for (int i = 0; i < 16; i++) {
            float ti = t[i];
#pragma unroll
            for (int j = 0; j < 16; j++) h[j] = fmaf(ti, W2s[i * 16 + j], h[j]);
        }
    }

    float z[16];
#pragma unroll
    for (int c = 0; c < 16; c++) z[c] = obs[c];
    for (int m = 0; m < 16; m++) {
        float e1m = h1[m];
        const float4* tbase = (const float4*)&T3s[(m * 16) * 16];
#pragma unroll
        for (int k2 = 0; k2 < 16; k2++) {
            float o = h0[k2] * e1m;
            float4 ta = tbase[k2 * 4 + 0];
            float4 tb = tbase[k2 * 4 + 1];
            float4 tc = tbase[k2 * 4 + 2];
            float4 td = tbase[k2 * 4 + 3];
            z[0]  = fmaf(o, ta.x, z[0]);  z[1]  = fmaf(o, ta.y, z[1]);
            z[2]  = fmaf(o, ta.z, z[2]);  z[3]  = fmaf(o, ta.w, z[3]);
            z[4]  = fmaf(o, tb.x, z[4]);  z[5]  = fmaf(o, tb.y, z[5]);
            z[6]  = fmaf(o, tb.z, z[6]);  z[7]  = fmaf(o, tb.w, z[7]);
            z[8]  = fmaf(o, tc.x, z[8]);  z[9]  = fmaf(o, tc.y, z[9]);
            z[10] = fmaf(o, tc.z, z[10]); z[11] = fmaf(o, tc.w, z[11]);
            z[12] = fmaf(o, td.x, z[12]); z[13] = fmaf(o, td.y, z[13]);
            z[14] = fmaf(o, td.z, z[14]); z[15] = fmaf(o, td.w, z[15]);
        }
    }

    float zz = bc2s;
#pragma unroll
    for (int j = 0; j < 16; j++) {
        float a = bc1s[j];
#pragma unroll
        for (int c = 0; c < 16; c++) a = fmaf(z[c], Wc1s[c * 16 + j], a);
        a = fmaxf(a, 0.0f);
        zz = fmaf(a, Wc2s[j], zz);
    }
    g_zbuf[b] = zz;
}

// ---------------------------------------------------------------------------
// gemm_mma: C = g1 @ Wp2 via split-bf16 3-pass mma.sync, fused epilogue.
// CTA: 64 rows x 512 cols, 512 threads = 16 warps arranged 2m x 8n.
// Warp tile: 32 rows (mt=2 m16 subtiles) x 64 cols (8 n8 tiles) -> each B
// fragment feeds 2 MMAs (register reuse), halving B ldmatrix traffic.
// K: 16 chunks of 32, 2-stage cp.async pipeline.
// ---------------------------------------------------------------------------
#define OFF_B    0
#define B_STAGE  65536
#define B_MAT    32768
#define OFF_A    131072
#define A_STAGE  10240
#define A_MAT    5120
#define OFF_WP1  151552
#define OFF_WP3  155648
#define OFF_PH   157696
#define OFF_RED  158208
#define SMEM_SZ  160256

__global__ __launch_bounds__(512, 1) void gemm_mma_kernel(
    const float* __restrict__ phenos,
    const float* __restrict__ Wp1,
    const float* __restrict__ Wp3,
    const float* __restrict__ bp3,
    float* __restrict__ out,
    int B)
{
    extern __shared__ __align__(1024) unsigned char smem[];
    const uint32_t sb = smem_u32(smem);
    const int tid  = threadIdx.x;
    const int wid  = tid >> 5;
    const int lane = tid & 31;
    const int wm   = wid >> 3;          // 0..1 (m: 32 rows each)
    const int wn   = wid & 7;           // 0..7 (n: 64 cols each)
    const int rowbase = blockIdx.x * 64;

    float*  wp1s = (float*)(smem + OFF_WP1);
    float*  wp3s = (float*)(smem + OFF_WP3);
    float2* ph2  = (float2*)(smem + OFF_PH);
    float*  red  = (float*)(smem + OFF_RED);

    for (int i = tid; i < 1024; i += 512) wp1s[i] = Wp1[i];
    wp3s[tid] = Wp3[tid];
    if (tid < 64) {
        int b = rowbase + tid;
        ph2[tid] = (b < B) ? ((const float2*)phenos)[b] : make_float2(0.f, 0.f);
    }
    __syncthreads();

    // ---- producer constants: A row pm, k-subblock pk (4 k each) ----
    const int pm = tid & 63;
    const int pk = tid >> 6;            // 0..7
    const float2 php = ph2[pm];

    // ---- ldmatrix lane address components ----
    const int g      = lane >> 3;
    const int rin16  = ((g & 1) << 3) + (lane & 7);
    const int a_lane = rin16 * 80 + ((g >> 1) << 4);
    const int b_krow = rin16;
    const int b_swz  = (b_krow & 7) << 4;
    const int b_colb = (wn * 128) + ((g >> 1) << 4);   // 64 cols = 128 bytes

    auto produce = [&](int c, int s) {
        // B tiles via cp.async (8 granules of 16B per thread)
        const uint32_t bdst = sb + OFF_B + s * B_STAGE;
#pragma unroll
        for (int i = 0; i < 8; i++) {
            int idx = tid + i * 512;          // 0..4095
            int mat = idx >> 11;
            int rem = idx & 2047;
            int k   = rem >> 6;
            int u   = rem & 63;
            const __nv_bfloat16* src =
                (mat == 0 ? g_Wh : g_Wl) + (c * 32 + k) * 512 + u * 8;
            uint32_t dst = bdst + mat * B_MAT + k * 1024 +
                           (((uint32_t)(u * 16)) ^ ((uint32_t)((k & 7) * 16)));
            CP_ASYNC16(dst, (const void*)src);
        }
        CP_COMMIT();
        // A tile: gelu(phenos @ Wp1), split bf16 hi/lo — 4 k per thread
        uint32_t hw[2], lw[2];
#pragma unroll
        for (int j = 0; j < 2; j++) {
            int k0 = c * 32 + pk * 4 + j * 2;
            float x0 = fmaf(php.y, wp1s[512 + k0],     php.x * wp1s[k0]);
            float x1 = fmaf(php.y, wp1s[512 + k0 + 1], php.x * wp1s[k0 + 1]);
            float g0 = gelu_fast(x0), g1v = gelu_fast(x1);
            __nv_bfloat16 h0 = __float2bfloat16(g0);
            __nv_bfloat16 h1 = __float2bfloat16(g1v);
            __nv_bfloat16 l0 = __float2bfloat16(g0 - __bfloat162float(h0));
            __nv_bfloat16 l1 = __float2bfloat16(g1v - __bfloat162float(h1));
            hw[j] = (uint32_t)__bfloat16_as_ushort(h0) |
                    ((uint32_t)__bfloat16_as_ushort(h1) << 16);
            lw[j] = (uint32_t)__bfloat16_as_ushort(l0) |
                    ((uint32_t)__bfloat16_as_ushort(l1) << 16);
        }
        uint32_t adst = sb + OFF_A + s * A_STAGE + pm * 80 + pk * 8;
        asm volatile("st.shared.v2.b32 [%0], {%1,%2};"
                     :: "r"(adst), "r"(hw[0]), "r"(hw[1]) : "memory");
        asm volatile("st.shared.v2.b32 [%0], {%1,%2};"
                     :: "r"(adst + A_MAT), "r"(lw[0]), "r"(lw[1]) : "memory");
    };

    float acc[2][8][4];
#pragma unroll
    for (int mt = 0; mt < 2; mt++)
#pragma unroll
        for (int n = 0; n < 8; n++)
#pragma unroll
            for (int r = 0; r < 4; r++) acc[mt][n][r] = 0.0f;

    produce(0, 0);

    for (int c = 0; c < 16; c++) {
        const int buf = c & 1;
        if (c + 1 < 16) produce(c + 1, buf ^ 1);
        else            CP_COMMIT();
        CP_WAIT1();
        __syncthreads();

        const uint32_t abase = sb + OFF_A + buf * A_STAGE +
                               (wm * 32) * 80 + a_lane;
        const uint32_t bbase = sb + OFF_B + buf * B_STAGE + b_krow * 1024;

#pragma unroll
        for (int ks = 0; ks < 2; ks++) {
            // A fragments for 2 m-subtiles, hi+lo
            uint32_t ah[2][4], al[2][4];
#pragma unroll
            for (int mt = 0; mt < 2; mt++) {
                uint32_t aa = abase + mt * 1280 + ks * 32;   // 16 rows * 80B
                LDMX4(ah[mt][0], ah[mt][1], ah[mt][2], ah[mt][3], aa);
                LDMX4(al[mt][0], al[mt][1], al[mt][2], al[mt][3], aa + A_MAT);
            }

#pragma unroll
            for (int nb = 0; nb < 4; nb++) {     // 4 blocks of 2 n-tiles
                uint32_t bh[2][2], bl[2][2];
                uint32_t coff = (uint32_t)(b_colb + nb * 32) ^ (uint32_t)b_swz;
                uint32_t ba = bbase + ks * 16384 + coff;
                LDMX4T(bh[0][0], bh[0][1], bh[1][0], bh[1][1], ba);
                LDMX4T(bl[0][0], bl[0][1], bl[1][0], bl[1][1], ba + B_MAT);
#pragma unroll
                for (int j = 0; j < 2; j++) {
#pragma unroll
                    for (int mt = 0; mt < 2; mt++)
                        MMA16816(acc[mt][nb * 2 + j], ah[mt], bh[j]);
                }
#pragma unroll
                for (int j = 0; j < 2; j++) {
#pragma unroll
                    for (int mt = 0; mt < 2; mt++)
                        MMA16816(acc[mt][nb * 2 + j], ah[mt], bl[j]);
                }
#pragma unroll
                for (int j = 0; j < 2; j++) {
#pragma unroll
                    for (int mt = 0; mt < 2; mt++)
                        MMA16816(acc[mt][nb * 2 + j], al[mt], bh[j]);
                }
            }
        }
        __syncthreads();
    }

    // ---- epilogue: gelu(C) @ Wp3, deterministic reduce, + z + bp3 ----
    const int q   = lane >> 2;
    const int idq = lane & 3;
#pragma unroll
    for (int mt = 0; mt < 2; mt++) {
        float p2[2] = {0.f, 0.f};
#pragma unroll
        for (int n = 0; n < 8; n++)
#pragma unroll
            for (int r = 0; r < 4; r++) {
                int col = wn * 64 + n * 8 + idq * 2 + (r & 1);
                p2[r >> 1] = fmaf(gelu_fast(acc[mt][n][r]), wp3s[col], p2[r >> 1]);
            }
#pragma unroll
        for (int i = 0; i < 2; i++) {
            float s = p2[i];
            s += __shfl_xor_sync(0xFFFFFFFF, s, 1);
            s += __shfl_xor_sync(0xFFFFFFFF, s, 2);
            if (idq == 0) {
                int row = wm * 32 + mt * 16 + i * 8 + q;
                red[row * 8 + wn] = s;
            }
        }
    }
    __syncthreads();
    if (tid < 64) {
        int b = rowbase + tid;
        if (b < B) {
            float s = 0.0f;
#pragma unroll
            for (int j = 0; j < 8; j++) s += red[tid * 8 + j];
            out[b] = g_zbuf[b] + s + bp3[0];
        }
    }
}

// ---------------------------------------------------------------------------
// Launch
// ---------------------------------------------------------------------------
extern "C" void kernel_launch(void* const* d_in, const int* in_sizes, int n_in,
                              void* d_out, int out_size) {
    const int*   x      = (const int*)  d_in[0];
    const float* phenos = (const float*)d_in[1];
    const float* emb    = (const float*)d_in[2];
    const float* W1     = (const float*)d_in[3];
    const float* b1     = (const float*)d_in[4];
    const float* W2     = (const float*)d_in[5];
    const float* b2     = (const float*)d_in[6];
    const float* Wb     = (const float*)d_in[7];
    const float* ob     = (const float*)d_in[8];
    const float* Wc1    = (const float*)d_in[9];
    const float* bc1    = (const float*)d_in[10];
    const float* Wc2    = (const float*)d_in[11];
    const float* bc2    = (const float*)d_in[12];
    const float* Wp1    = (const float*)d_in[13];
    const float* Wp2    = (const float*)d_in[14];
    const float* Wp3    = (const float*)d_in[15];
    const float* bp3    = (const float*)d_in[16];
    float* out = (float*)d_out;

    int B = in_sizes[0] / 2;

    cudaFuncSetAttribute(gemm_mma_kernel,
                         cudaFuncAttributeMaxDynamicSharedMemorySize, SMEM_SZ);

    prep_T_kernel<<<16, 256>>>(Wb);
    prep_W_kernel<<<1024, 256>>>(Wp2);
    zpath_kernel<<<(B + 255) / 256, 256>>>(x, emb, W1, b1, W2, b2, ob,
                                           Wc1, bc1, Wc2, bc2, B);
    gemm_mma_kernel<<<(B + 63) / 64, 512, SMEM_SZ>>>(phenos, Wp1, Wp3, bp3,
                                                     out, B);
}

// round 6
// speedup vs baseline: 2.6092x; 1.0455x over previous
#include <cuda_runtime.h>
#include <cuda_bf16.h>
#include <math.h>
#include <stdint.h>

// ---------------------------------------------------------------------------
// Device scratch (declared statically; no dynamic allocation)
// ---------------------------------------------------------------------------
__device__ float g_T2[4096];                    // folded bilinear tensor
__device__ float g_zbuf[1 << 17];               // per-row z scalar
__device__ __nv_bfloat16 g_Wh[512 * 512];       // Wp2 split hi (layout [k][n])
__device__ __nv_bfloat16 g_Wl[512 * 512];       // Wp2 split lo (layout [k][n])

// ---------------------------------------------------------------------------
// Helpers
// ---------------------------------------------------------------------------
__device__ __forceinline__ uint32_t smem_u32(const void* p) {
    uint32_t a;
    asm("{ .reg .u64 t; cvta.to.shared.u64 t, %1; cvt.u32.u64 %0, t; }"
        : "=r"(a) : "l"(p));
    return a;
}

// Branch-free gelu, exact-erf via Abramowitz-Stegun 7.1.26 (|err| <= 1.5e-7)
__device__ __forceinline__ float gelu_fast(float x) {
    float ax = fabsf(x);
    float z  = ax * 0.70710678118654752440f;
    float t  = __fdividef(1.0f, fmaf(0.3275911f, z, 1.0f));
    float e  = __expf(-z * z);
    float y  = fmaf(t, 1.061405429f, -1.453152027f);
    y = fmaf(y, t, 1.421413741f);
    y = fmaf(y, t, -0.284496736f);
    y = fmaf(y, t, 0.254829592f);
    y = y * t * e;                       // 1 - erf(z)
    float erfv = 1.0f - y;               // erf(|x|/sqrt(2))
    return 0.5f * fmaf(ax, erfv, x);
}

#define LDMX4(r0, r1, r2, r3, a)                                              \
    asm volatile("ldmatrix.sync.aligned.m8n8.x4.shared.b16 {%0,%1,%2,%3}, [%4];" \
                 : "=r"(r0), "=r"(r1), "=r"(r2), "=r"(r3) : "r"(a))

#define LDMX4T(r0, r1, r2, r3, a)                                             \
    asm volatile("ldmatrix.sync.aligned.m8n8.x4.trans.shared.b16 {%0,%1,%2,%3}, [%4];" \
                 : "=r"(r0), "=r"(r1), "=r"(r2), "=r"(r3) : "r"(a))

#define MMA16816(d, a, b)                                                     \
    asm("mma.sync.aligned.m16n8k16.row.col.f32.bf16.bf16.f32 "               \
        "{%0,%1,%2,%3}, {%4,%5,%6,%7}, {%8,%9}, {%0,%1,%2,%3};"               \
        : "+f"((d)[0]), "+f"((d)[1]), "+f"((d)[2]), "+f"((d)[3])              \
        : "r"((a)[0]), "r"((a)[1]), "r"((a)[2]), "r"((a)[3]),                 \
          "r"((b)[0]), "r"((b)[1]))

#define CP_ASYNC16(dst, src)                                                  \
    asm volatile("cp.async.cg.shared.global [%0], [%1], 16;"                  \
                 :: "r"(dst), "l"(src) : "memory")

#define CP_COMMIT() asm volatile("cp.async.commit_group;" ::: "memory")
#define CP_WAIT1()  asm volatile("cp.async.wait_group 1;" ::: "memory")

// ---------------------------------------------------------------------------
// prep_T: T[c,k,m] = sum_a Wb[c,a,k]*Wb[a,c,m]
// ---------------------------------------------------------------------------
__global__ void prep_T_kernel(const float* __restrict__ Wb) {
    int t = blockIdx.x * blockDim.x + threadIdx.x;
    if (t >= 4096) return;
    int c = t & 15, k = (t >> 4) & 15, m = (t >> 8) & 15;
    float acc = 0.0f;
#pragma unroll
    for (int a = 0; a < 16; a++)
        acc = fmaf(Wb[c * 256 + a * 16 + k], Wb[a * 256 + c * 16 + m], acc);
    g_T2[(m * 16 + k) * 16 + c] = acc;
}

// ---------------------------------------------------------------------------
// prep_W: split Wp2 into bf16 hi/lo (same [k][n] layout)
// ---------------------------------------------------------------------------
__global__ void prep_W_kernel(const float* __restrict__ Wp2) {
    int t = blockIdx.x * blockDim.x + threadIdx.x;   // 262144
    float w = Wp2[t];
    __nv_bfloat16 hb = __float2bfloat16(w);
    __nv_bfloat16 lb = __float2bfloat16(w - __bfloat162float(hb));
    g_Wh[t] = hb;
    g_Wl[t] = lb;
}

// ---------------------------------------------------------------------------
// zpath (known good)
// ---------------------------------------------------------------------------
__global__ __launch_bounds__(256) void zpath_kernel(
    const int*   __restrict__ xg,
    const float* __restrict__ emb,
    const float* __restrict__ W1,  const float* __restrict__ b1,
    const float* __restrict__ W2,  const float* __restrict__ b2,
    const float* __restrict__ ob,
    const float* __restrict__ Wc1, const float* __restrict__ bc1,
    const float* __restrict__ Wc2, const float* __restrict__ bc2,
    int B)
{
    __shared__ float W1s[256], W2s[256], Wc1s[256];
    __shared__ float T3s[4096];
    __shared__ float b1s[16], b2s[16], obs[16], bc1s[16], Wc2s[16];
    __shared__ float bc2s;

    int tid = threadIdx.x;
    W1s[tid]  = W1[tid];
    W2s[tid]  = W2[tid];
    Wc1s[tid] = Wc1[tid];
    for (int i = tid; i < 4096; i += 256) T3s[i] = g_T2[i];
    if (tid < 16) {
        b1s[tid] = b1[tid]; b2s[tid] = b2[tid]; obs[tid] = ob[tid];
        bc1s[tid] = bc1[tid]; Wc2s[tid] = Wc2[tid];
    }
    if (tid == 0) bc2s = bc2[0];
    __syncthreads();

    int b = blockIdx.x * 256 + tid;
    if (b >= B) return;
    int2 xi = ((const int2*)xg)[b];

    float h0[16], h1[16];
#pragma unroll
    for (int s = 0; s < 2; s++) {
        long row = (s == 0) ? (long)xi.x : (long)xi.y;
        const float4* ep = (const float4*)(emb + row * 16);
        float4 E0 = ep[0], E1 = ep[1], E2 = ep[2], E3 = ep[3];
        float e[16] = {E0.x, E0.y, E0.z, E0.w, E1.x, E1.y, E1.z, E1.w,
                       E2.x, E2.y, E2.z, E2.w, E3.x, E3.y, E3.z, E3.w};
        float t[16];
#pragma unroll
        for (int j = 0; j < 16; j++) t[j] = b1s[j];
#pragma unroll
        for (int i = 0; i < 16; i++) {
            float ei = e[i];
#pragma unroll
            for (int j = 0; j < 16; j++) t[j] = fmaf(ei, W1s[i * 16 + j], t[j]);
        }
#pragma unroll
        for (int j = 0; j < 16; j++) t[j] = fmaxf(t[j], 0.0f);
        float* h = (s == 0) ? h0 : h1;
#pragma unroll
        for (int j = 0; j < 16; j++) h[j] = b2s[j];
#pragma unroll
        for (int i = 0; i < 16; i++) {
            float ti = t[i];
#pragma unroll
            for (int j = 0; j < 16; j++) h[j] = fmaf(ti, W2s[i * 16 + j], h[j]);
        }
    }

    float z[16];
#pragma unroll
    for (int c = 0; c < 16; c++) z[c] = obs[c];
    for (int m = 0; m < 16; m++) {
        float e1m = h1[m];
        const float4* tbase = (const float4*)&T3s[(m * 16) * 16];
#pragma unroll
        for (int k2 = 0; k2 < 16; k2++) {
            float o = h0[k2] * e1m;
            float4 ta = tbase[k2 * 4 + 0];
            float4 tb = tbase[k2 * 4 + 1];
            float4 tc = tbase[k2 * 4 + 2];
            float4 td = tbase[k2 * 4 + 3];
            z[0]  = fmaf(o, ta.x, z[0]);  z[1]  = fmaf(o, ta.y, z[1]);
            z[2]  = fmaf(o, ta.z, z[2]);  z[3]  = fmaf(o, ta.w, z[3]);
            z[4]  = fmaf(o, tb.x, z[4]);  z[5]  = fmaf(o, tb.y, z[5]);
            z[6]  = fmaf(o, tb.z, z[6]);  z[7]  = fmaf(o, tb.w, z[7]);
            z[8]  = fmaf(o, tc.x, z[8]);  z[9]  = fmaf(o, tc.y, z[9]);
            z[10] = fmaf(o, tc.z, z[10]); z[11] = fmaf(o, tc.w, z[11]);
            z[12] = fmaf(o, td.x, z[12]); z[13] = fmaf(o, td.y, z[13]);
            z[14] = fmaf(o, td.z, z[14]); z[15] = fmaf(o, td.w, z[15]);
        }
    }

    float zz = bc2s;
#pragma unroll
    for (int j = 0; j < 16; j++) {
        float a = bc1s[j];
#pragma unroll
        for (int c = 0; c < 16; c++) a = fmaf(z[c], Wc1s[c * 16 + j], a);
        a = fmaxf(a, 0.0f);
        zz = fmaf(a, Wc2s[j], zz);
    }
    g_zbuf[b] = zz;
}

// ---------------------------------------------------------------------------
// gemm_mma: C = g1 @ Wp2 via split-bf16 3-pass mma.sync, fused epilogue.
// CTA: 64 rows x 512 cols, 512 threads = 16 warps arranged 2m x 8n.
// Warp tile: 32 rows x 64 cols. K: 16 chunks of 32.
// 3-stage smem ring, exactly ONE __syncthreads() per chunk (lag-2 stage
// reuse is ordered by the previous chunk's barrier).
// ---------------------------------------------------------------------------
#define OFF_B    0
#define B_STAGE  65536
#define B_MAT    32768
#define OFF_A    196608
#define A_STAGE  10240
#define A_MAT    5120
#define OFF_WP1  227328
#define OFF_PH   231424
#define SMEM_SZ  231936
// epilogue overlays (B stage 0 is dead after the mainloop):
#define OFF_WP3E 0
#define OFF_RED  2048

__global__ __launch_bounds__(512, 1) void gemm_mma_kernel(
    const float* __restrict__ phenos,
    const float* __restrict__ Wp1,
    const float* __restrict__ Wp3,
    const float* __restrict__ bp3,
    float* __restrict__ out,
    int B)
{
    extern __shared__ __align__(1024) unsigned char smem[];
    const uint32_t sb = smem_u32(smem);
    const int tid  = threadIdx.x;
    const int wid  = tid >> 5;
    const int lane = tid & 31;
    const int wm   = wid >> 3;          // 0..1 (m: 32 rows each)
    const int wn   = wid & 7;           // 0..7 (n: 64 cols each)
    const int rowbase = blockIdx.x * 64;

    float*  wp1s = (float*)(smem + OFF_WP1);
    float2* ph2  = (float2*)(smem + OFF_PH);

    for (int i = tid; i < 1024; i += 512) wp1s[i] = Wp1[i];
    if (tid < 64) {
        int b = rowbase + tid;
        ph2[tid] = (b < B) ? ((const float2*)phenos)[b] : make_float2(0.f, 0.f);
    }
    __syncthreads();

    // ---- producer constants ----
    const int pm = tid & 63;            // A row produced by this thread
    const int pk = tid >> 6;            // 0..7: k sub-block (4 k each)
    const float2 php = ph2[pm];
    // B cp.async: u (n-octet) is constant per thread -> swizzle term constant
    const int pu = tid & 63;            // n-octet index (8 bf16 each)
    const int pkt = tid >> 6;           // base k row (0..7), k = pkt + 8j
    const uint32_t pswz = (uint32_t)(pu * 16) ^ (uint32_t)(pkt * 16);

    // ---- ldmatrix lane address components ----
    const int g      = lane >> 3;
    const int rin16  = ((g & 1) << 3) + (lane & 7);
    const int a_lane = rin16 * 80 + ((g >> 1) << 4);
    const int b_krow = rin16;
    const int b_swz  = (b_krow & 7) << 4;
    const int b_colb = (wn * 128) + ((g >> 1) << 4);   // 64 cols = 128 bytes

    auto produce = [&](int c, int s) {
        // B tiles via cp.async: affine addresses, mat fixed per sub-loop
        const uint32_t bdst = sb + OFF_B + s * B_STAGE;
        {
            const __nv_bfloat16* srch = g_Wh + (c * 32 + pkt) * 512 + pu * 8;
            const __nv_bfloat16* srcl = g_Wl + (c * 32 + pkt) * 512 + pu * 8;
            uint32_t dsth = bdst + pkt * 1024 + pswz;
#pragma unroll
            for (int j = 0; j < 4; j++)
                CP_ASYNC16(dsth + j * 8192, (const void*)(srch + j * 4096));
            uint32_t dstl = bdst + B_MAT + pkt * 1024 + pswz;
#pragma unroll
            for (int j = 0; j < 4; j++)
                CP_ASYNC16(dstl + j * 8192, (const void*)(srcl + j * 4096));
        }
        CP_COMMIT();
        // A tile: gelu(phenos @ Wp1), split bf16 hi/lo — 4 k per thread
        uint32_t hw[2], lw[2];
#pragma unroll
        for (int j = 0; j < 2; j++) {
            int k0 = c * 32 + pk * 4 + j * 2;
            float x0 = fmaf(php.y, wp1s[512 + k0],     php.x * wp1s[k0]);
            float x1 = fmaf(php.y, wp1s[512 + k0 + 1], php.x * wp1s[k0 + 1]);
            float g0 = gelu_fast(x0), g1v = gelu_fast(x1);
            __nv_bfloat16 h0 = __float2bfloat16(g0);
            __nv_bfloat16 h1 = __float2bfloat16(g1v);
            __nv_bfloat16 l0 = __float2bfloat16(g0 - __bfloat162float(h0));
            __nv_bfloat16 l1 = __float2bfloat16(g1v - __bfloat162float(h1));
            hw[j] = (uint32_t)__bfloat16_as_ushort(h0) |
                    ((uint32_t)__bfloat16_as_ushort(h1) << 16);
            lw[j] = (uint32_t)__bfloat16_as_ushort(l0) |
                    ((uint32_t)__bfloat16_as_ushort(l1) << 16);
        }
        uint32_t adst = sb + OFF_A + s * A_STAGE + pm * 80 + pk * 8;
        asm volatile("st.shared.v2.b32 [%0], {%1,%2};"
                     :: "r"(adst), "r"(hw[0]), "r"(hw[1]) : "memory");
        asm volatile("st.shared.v2.b32 [%0], {%1,%2};"
                     :: "r"(adst + A_MAT), "r"(lw[0]), "r"(lw[1]) : "memory");
    };

    float acc[2][8][4];
#pragma unroll
    for (int mt = 0; mt < 2; mt++)
#pragma unroll
        for (int n = 0; n < 8; n++)
#pragma unroll
            for (int r = 0; r < 4; r++) acc[mt][n][r] = 0.0f;

    produce(0, 0);

    int s = 0;          // stage of current chunk
    for (int c = 0; c < 16; c++) {
        int snext = (s == 2) ? 0 : s + 1;
        if (c + 1 < 16) produce(c + 1, snext);
        else            CP_COMMIT();
        CP_WAIT1();
        __syncthreads();          // the ONLY barrier per chunk

        const uint32_t abase = sb + OFF_A + s * A_STAGE + (wm * 32) * 80 + a_lane;
        const uint32_t bbase = sb + OFF_B + s * B_STAGE + b_krow * 1024;

#pragma unroll
        for (int ks = 0; ks < 2; ks++) {
            uint32_t ah[2][4], al[2][4];
#pragma unroll
            for (int mt = 0; mt < 2; mt++) {
                uint32_t aa = abase + mt * 1280 + ks * 32;   // 16 rows * 80B
                LDMX4(ah[mt][0], ah[mt][1], ah[mt][2], ah[mt][3], aa);
                LDMX4(al[mt][0], al[mt][1], al[mt][2], al[mt][3], aa + A_MAT);
            }

#pragma unroll
            for (int nb = 0; nb < 4; nb++) {     // 4 blocks of 2 n-tiles
                uint32_t bh[2][2], bl[2][2];
                uint32_t coff = (uint32_t)(b_colb + nb * 32) ^ (uint32_t)b_swz;
                uint32_t ba = bbase + ks * 16384 + coff;
                LDMX4T(bh[0][0], bh[0][1], bh[1][0], bh[1][1], ba);
                LDMX4T(bl[0][0], bl[0][1], bl[1][0], bl[1][1], ba + B_MAT);
#pragma unroll
                for (int j = 0; j < 2; j++)
#pragma unroll
                    for (int mt = 0; mt < 2; mt++)
                        MMA16816(acc[mt][nb * 2 + j], ah[mt], bh[j]);
#pragma unroll
                for (int j = 0; j < 2; j++)
#pragma unroll
                    for (int mt = 0; mt < 2; mt++)
                        MMA16816(acc[mt][nb * 2 + j], ah[mt], bl[j]);
#pragma unroll
                for (int j = 0; j < 2; j++)
#pragma unroll
                    for (int mt = 0; mt < 2; mt++)
                        MMA16816(acc[mt][nb * 2 + j], al[mt], bh[j]);
            }
        }
        s = snext;
    }

    // ---- epilogue: gelu(C) @ Wp3, deterministic reduce, + z + bp3 ----
    __syncthreads();                      // all MMAs done; B stages now dead
    float* wp3s = (float*)(smem + OFF_WP3E);
    float* red  = (float*)(smem + OFF_RED);
    wp3s[tid] = Wp3[tid];
    __syncthreads();

    const int q   = lane >> 2;
    const int idq = lane & 3;
#pragma unroll
    for (int mt = 0; mt < 2; mt++) {
        float p2[2] = {0.f, 0.f};
#pragma unroll
        for (int n = 0; n < 8; n++)
#pragma unroll
            for (int r = 0; r < 4; r++) {
                int col = wn * 64 + n * 8 + idq * 2 + (r & 1);
                p2[r >> 1] = fmaf(gelu_fast(acc[mt][n][r]), wp3s[col], p2[r >> 1]);
            }
#pragma unroll
        for (int i = 0; i < 2; i++) {
            float sv = p2[i];
            sv += __shfl_xor_sync(0xFFFFFFFF, sv, 1);
            sv += __shfl_xor_sync(0xFFFFFFFF, sv, 2);
            if (idq == 0) {
                int row = wm * 32 + mt * 16 + i * 8 + q;
                red[row * 8 + wn] = sv;
            }
        }
    }
    __syncthreads();
    if (tid < 64) {
        int b = rowbase + tid;
        if (b < B) {
            float sv = 0.0f;
#pragma unroll
            for (int j = 0; j < 8; j++) sv += red[tid * 8 + j];
            out[b] = g_zbuf[b] + sv + bp3[0];
        }
    }
}

// ---------------------------------------------------------------------------
// Launch
// ---------------------------------------------------------------------------
extern "C" void kernel_launch(void* const* d_in, const int* in_sizes, int n_in,
                              void* d_out, int out_size) {
    const int*   x      = (const int*)  d_in[0];
    const float* phenos = (const float*)d_in[1];
    const float* emb    = (const float*)d_in[2];
    const float* W1     = (const float*)d_in[3];
    const float* b1     = (const float*)d_in[4];
    const float* W2     = (const float*)d_in[5];
    const float* b2     = (const float*)d_in[6];
    const float* Wb     = (const float*)d_in[7];
    const float* ob     = (const float*)d_in[8];
    const float* Wc1    = (const float*)d_in[9];
    const float* bc1    = (const float*)d_in[10];
    const float* Wc2    = (const float*)d_in[11];
    const float* bc2    = (const float*)d_in[12];
    const float* Wp1    = (const float*)d_in[13];
    const float* Wp2    = (const float*)d_in[14];
    const float* Wp3    = (const float*)d_in[15];
    const float* bp3    = (const float*)d_in[16];
    float* out = (float*)d_out;

    int B = in_sizes[0] / 2;

    cudaFuncSetAttribute(gemm_mma_kernel,
                         cudaFuncAttributeMaxDynamicSharedMemorySize, SMEM_SZ);

    prep_T_kernel<<<16, 256>>>(Wb);
    prep_W_kernel<<<1024, 256>>>(Wp2);
    zpath_kernel<<<(B + 255) / 256, 256>>>(x, emb, W1, b1, W2, b2, ob,
                                           Wc1, bc1, Wc2, bc2, B);
    gemm_mma_kernel<<<(B + 63) / 64, 512, SMEM_SZ>>>(phenos, Wp1, Wp3, bp3,
                                                     out, B);
}